// round 10
// baseline (speedup 1.0000x reference)
#include <cuda_runtime.h>
#include <math.h>
#include <stdint.h>

#define B_  4
#define T_  1024
#define C_  1024
#define H_  16
#define DH_ 64
#define M_  4096   /* B*T */

// ---------------- scratch (static __device__, no allocations) ----------------
__device__ float g_q[(size_t)M_ * C_];
__device__ float g_k[(size_t)M_ * C_];
__device__ float g_v[(size_t)M_ * C_];
__device__ float g_y[(size_t)M_ * C_];
__device__ float g_xt[(size_t)M_ * C_];          // tf32-rounded x
__device__ float g_wt[4][(size_t)C_ * C_];       // tf32-rounded Wq,Wk,Wv,Wo
__device__ float g_maskf[(size_t)B_ * T_ * T_];  // additive mask: 0 or -FLT_MAX
__device__ int g_mask_mode;   // 0 = u8 bytes, 1 = int32, 2 = float32

#define NEGF (-3.402823466e38f)

// ---------------- small helpers ----------------
__device__ __forceinline__ float to_tf32(float x) {
    uint32_t r;
    asm("cvt.rna.tf32.f32 %0, %1;" : "=r"(r) : "f"(x));
    return __uint_as_float(r);
}

__device__ __forceinline__ void mma8(float* c, const float* a, const float* b) {
    asm volatile(
        "mma.sync.aligned.m16n8k8.row.col.f32.tf32.tf32.f32 "
        "{%0,%1,%2,%3}, {%4,%5,%6,%7}, {%8,%9}, {%0,%1,%2,%3};"
        : "+f"(c[0]), "+f"(c[1]), "+f"(c[2]), "+f"(c[3])
        : "r"(__float_as_uint(a[0])), "r"(__float_as_uint(a[1])),
          "r"(__float_as_uint(a[2])), "r"(__float_as_uint(a[3])),
          "r"(__float_as_uint(b[0])), "r"(__float_as_uint(b[1])));
}

__device__ __forceinline__ void cp16(void* smem, const void* gmem) {
    uint32_t s = (uint32_t)__cvta_generic_to_shared(smem);
    asm volatile("cp.async.cg.shared.global [%0], [%1], 16;" :: "r"(s), "l"(gmem));
}
__device__ __forceinline__ void cp_commit() { asm volatile("cp.async.commit_group;"); }
template <int N>
__device__ __forceinline__ void cp_wait() { asm volatile("cp.async.wait_group %0;" :: "n"(N)); }

// ---------------- mask dtype probe + normalize ----------------
__global__ void probe_mask_kernel(const unsigned char* __restrict__ m) {
    __shared__ int s_gt1, s_nzoff;
    if (threadIdx.x == 0) { s_gt1 = 0; s_nzoff = 0; }
    __syncthreads();
    int gt1 = 0, nz = 0;
    for (int i = threadIdx.x; i < 262144; i += blockDim.x) {
        unsigned char v = m[i];
        if (v > 1) gt1 = 1;
        else if (v && (i & 3)) nz = 1;
    }
    if (gt1) atomicOr(&s_gt1, 1);
    if (nz)  atomicOr(&s_nzoff, 1);
    __syncthreads();
    if (threadIdx.x == 0)
        g_mask_mode = s_gt1 ? 2 : (s_nzoff ? 0 : 1);
}

__global__ void normalize_mask_kernel(const void* __restrict__ m) {
    int i = blockIdx.x * blockDim.x + threadIdx.x;
    int mode = g_mask_mode;
    bool keep;
    if (mode == 1)      keep = ((const int*)m)[i]   != 0;
    else if (mode == 2) keep = ((const float*)m)[i] != 0.0f;
    else                keep = ((const unsigned char*)m)[i] != 0;
    g_maskf[i] = keep ? 0.0f : NEGF;
}

// ---------------- pre-round GEMM inputs to tf32 ----------------
__global__ void round_inputs_kernel(const float* __restrict__ x,
                                    const float* __restrict__ wq,
                                    const float* __restrict__ wk,
                                    const float* __restrict__ wv,
                                    const float* __restrict__ wo) {
    int i = blockIdx.x * blockDim.x + threadIdx.x;   // 0 .. 8M-1
    if (i < M_ * C_) {
        g_xt[i] = to_tf32(x[i]);
    } else {
        int j = i - M_ * C_;
        int w = j >> 20;                  // C_*C_ = 2^20
        int r = j & (C_ * C_ - 1);
        const float* src = (w == 0) ? wq : (w == 1) ? wk : (w == 2) ? wv : wo;
        g_wt[w][r] = to_tf32(src[r]);
    }
}

// ---------------- tf32 mma NT GEMM: Out[m][n] = sum_k A[m][k]*W[n][k] ----------------
// 128x128 CTA tile, 256 threads (8 warps 4x2), warp tile 32x64, k-tile 16, cp.async dbuf.
#define GS 20   /* SMEM row stride (floats): conflict-free frag loads */

__device__ __forceinline__ void gemm256(const float* __restrict__ A,
                                        const float* __restrict__ W,
                                        float* __restrict__ Out,
                                        float scale,
                                        const float* __restrict__ bias,
                                        int do_round) {
    __shared__ float As[2][128 * GS];
    __shared__ float Bs[2][128 * GS];
    const int tid  = threadIdx.x;
    const int warp = tid >> 5, lane = tid & 31;
    const int g = lane >> 2, tg = lane & 3;
    const int wm = warp >> 1, wn = warp & 1;
    const int m0 = blockIdx.y * 128, n0 = blockIdx.x * 128;

    float acc[2][8][4];
#pragma unroll
    for (int mf = 0; mf < 2; mf++)
#pragma unroll
        for (int nf = 0; nf < 8; nf++)
#pragma unroll
            for (int q = 0; q < 4; q++) acc[mf][nf][q] = 0.0f;

#pragma unroll
    for (int i = 0; i < 2; i++) {       // prologue: tile 0 (128 rows x 16 floats)
        int chunk = i * 256 + tid, row = chunk >> 2, c4 = (chunk & 3) * 4;
        cp16(&As[0][row * GS + c4], A + (size_t)(m0 + row) * C_ + c4);
        cp16(&Bs[0][row * GS + c4], W + (size_t)(n0 + row) * C_ + c4);
    }
    cp_commit();

    for (int kt = 0; kt < 64; kt++) {
        int buf = kt & 1;
        if (kt < 63) {
#pragma unroll
            for (int i = 0; i < 2; i++) {
                int chunk = i * 256 + tid, row = chunk >> 2, c4 = (chunk & 3) * 4;
                cp16(&As[buf ^ 1][row * GS + c4],
                     A + (size_t)(m0 + row) * C_ + (kt + 1) * 16 + c4);
                cp16(&Bs[buf ^ 1][row * GS + c4],
                     W + (size_t)(n0 + row) * C_ + (kt + 1) * 16 + c4);
            }
            cp_commit();
            cp_wait<1>();
        } else {
            cp_wait<0>();
        }
        __syncthreads();
        const float* as = As[buf];
        const float* bs = Bs[buf];
#pragma unroll
        for (int ks = 0; ks < 2; ks++) {
            const int k0 = ks * 8;
            float a[2][4], b[8][2];
#pragma unroll
            for (int mf = 0; mf < 2; mf++) {
                int r = wm * 32 + mf * 16 + g;
                a[mf][0] = as[r * GS + k0 + tg];
                a[mf][1] = as[(r + 8) * GS + k0 + tg];
                a[mf][2] = as[r * GS + k0 + tg + 4];
                a[mf][3] = as[(r + 8) * GS + k0 + tg + 4];
            }
#pragma unroll
            for (int nf = 0; nf < 8; nf++) {
                int c = wn * 64 + nf * 8 + g;
                b[nf][0] = bs[c * GS + k0 + tg];
                b[nf][1] = bs[c * GS + k0 + tg + 4];
            }
#pragma unroll
            for (int mf = 0; mf < 2; mf++)
#pragma unroll
                for (int nf = 0; nf < 8; nf++)
                    mma8(acc[mf][nf], a[mf], b[nf]);
        }
        __syncthreads();
    }

#pragma unroll
    for (int mf = 0; mf < 2; mf++) {
        int r0 = m0 + wm * 32 + mf * 16 + g;
#pragma unroll
        for (int nf = 0; nf < 8; nf++) {
            int c = n0 + wn * 64 + nf * 8 + 2 * tg;
            float v0 = acc[mf][nf][0] * scale, v1 = acc[mf][nf][1] * scale;
            float v2 = acc[mf][nf][2] * scale, v3 = acc[mf][nf][3] * scale;
            if (bias) { v0 += bias[c]; v1 += bias[c + 1]; v2 += bias[c]; v3 += bias[c + 1]; }
            if (do_round) { v0 = to_tf32(v0); v1 = to_tf32(v1); v2 = to_tf32(v2); v3 = to_tf32(v3); }
            *(float2*)(Out + (size_t)r0 * C_ + c)       = make_float2(v0, v1);
            *(float2*)(Out + (size_t)(r0 + 8) * C_ + c) = make_float2(v2, v3);
        }
    }
}

__global__ __launch_bounds__(256, 2) void qkv_mma_kernel() {
    if (blockIdx.z == 0)      gemm256(g_xt, g_wt[0], g_q, 0.125f, nullptr, 1);
    else if (blockIdx.z == 1) gemm256(g_xt, g_wt[1], g_k, 1.0f,  nullptr, 1);
    else                      gemm256(g_xt, g_wt[2], g_v, 1.0f,  nullptr, 1);
}

__global__ __launch_bounds__(256, 2) void proj_mma_kernel(const float* __restrict__ bo,
                                                          float* __restrict__ out) {
    gemm256(g_y, g_wt[3], out, 1.0f, bo, 0);
}

// ---------------- tf32 mma flash attention ----------------
// grid (T/64, B*H), 128 threads. Warp w owns rows [16w,16w+16) x all 64 cols.
// Q fragments in registers. Dynamic SMEM: QP (Q stage, then P), K dbuf, V dbuf.
// K stride 68, V row-major stride 72, QP stride 68 -> all frag LDS conflict-free.
#define QP_OFF 0
#define K_OFF  4352            /* 64*68 */
#define K_SZ   4352
#define V_OFF  13056           /* K_OFF + 2*K_SZ */
#define V_SZ   4608            /* 64*72 */
#define ATTN_SMEM_BYTES ((13056 + 2 * 4608) * 4)   /* 89088 */

__global__ __launch_bounds__(128) void attn_mma_kernel() {
    extern __shared__ float sm[];
    float* QP = sm + QP_OFF;
    const int tid  = threadIdx.x;
    const int warp = tid >> 5, lane = tid & 31;
    const int g = lane >> 2, tg = lane & 3;
    const int i0 = warp * 16;
    const int bh = blockIdx.y, b = bh >> 4, h = bh & 15;
    const int q0 = blockIdx.x * 64;

    const float* qg = g_q + (size_t)(b * T_ + q0) * C_ + h * DH_;
    const float* kg = g_k + (size_t)(b * T_) * C_ + h * DH_;
    const float* vg = g_v + (size_t)(b * T_) * C_ + h * DH_;
    const float* mrow0f = g_maskf + (size_t)(b * T_ + q0 + i0 + g) * T_;
    const float* mrow1f = mrow0f + (size_t)8 * T_;

    // stage Q tile into QP (64 rows x 64 floats = 1024 float4 chunks)
#pragma unroll
    for (int i = 0; i < 8; i++) {
        int chunk = i * 128 + tid, row = chunk >> 4, c4 = (chunk & 15) * 4;
        float4 v = *(const float4*)(qg + (size_t)row * C_ + c4);
        *(float4*)&QP[row * 68 + c4] = v;
    }
    // prefetch K/V tile 0 into buffer 0 (full 64x64 tiles!)
#pragma unroll
    for (int i = 0; i < 8; i++) {
        int chunk = i * 128 + tid, row = chunk >> 4, c4 = (chunk & 15) * 4;
        cp16(&sm[K_OFF + row * 68 + c4], kg + (size_t)row * C_ + c4);
        cp16(&sm[V_OFF + row * 72 + c4], vg + (size_t)row * C_ + c4);
    }
    cp_commit();
    __syncthreads();   // Q staging visible

    float qa[8][4];
#pragma unroll
    for (int kk = 0; kk < 8; kk++) {
        qa[kk][0] = QP[(i0 + g) * 68 + kk * 8 + tg];
        qa[kk][1] = QP[(i0 + g + 8) * 68 + kk * 8 + tg];
        qa[kk][2] = QP[(i0 + g) * 68 + kk * 8 + tg + 4];
        qa[kk][3] = QP[(i0 + g + 8) * 68 + kk * 8 + tg + 4];
    }

    float o[8][4];
#pragma unroll
    for (int f = 0; f < 8; f++)
#pragma unroll
        for (int q = 0; q < 4; q++) o[f][q] = 0.0f;
    float mi0 = NEGF, mi1 = NEGF, li0 = 0.0f, li1 = 0.0f;

    for (int it = 0; it < 16; it++) {
        const int bb = it & 1;
        const float* Kb = sm + K_OFF + bb * K_SZ;
        const float* Vb = sm + V_OFF + bb * V_SZ;
        cp_wait<0>();
        __syncthreads();   // tile ready; all warps done with prev iter's buffers
        if (it < 15) {     // prefetch next tile into other buffer
            const float* kn = kg + (size_t)(it + 1) * 64 * C_;
            const float* vn = vg + (size_t)(it + 1) * 64 * C_;
            float* Kn = sm + K_OFF + (bb ^ 1) * K_SZ;
            float* Vn = sm + V_OFF + (bb ^ 1) * V_SZ;
#pragma unroll
            for (int i = 0; i < 8; i++) {
                int chunk = i * 128 + tid, row = chunk >> 4, c4 = (chunk & 15) * 4;
                cp16(&Kn[row * 68 + c4], kn + (size_t)row * C_ + c4);
                cp16(&Vn[row * 72 + c4], vn + (size_t)row * C_ + c4);
            }
            cp_commit();
        }

        // S = Q K^T (16x64 per warp)
        float s[8][4];
#pragma unroll
        for (int f = 0; f < 8; f++)
#pragma unroll
            for (int q = 0; q < 4; q++) s[f][q] = 0.0f;
#pragma unroll
        for (int kk = 0; kk < 8; kk++) {
#pragma unroll
            for (int f = 0; f < 8; f++) {
                float bbk[2];
                bbk[0] = Kb[(f * 8 + g) * 68 + kk * 8 + tg];
                bbk[1] = Kb[(f * 8 + g) * 68 + kk * 8 + tg + 4];
                mma8(s[f], qa[kk], bbk);
            }
        }

        // additive mask + row max
        const int jt = it * 64;
        float mx0 = NEGF, mx1 = NEGF;
#pragma unroll
        for (int f = 0; f < 8; f++) {
            int c = jt + f * 8 + 2 * tg;
            float2 m0 = *(const float2*)(mrow0f + c);
            float2 m1 = *(const float2*)(mrow1f + c);
            s[f][0] += m0.x; s[f][1] += m0.y;
            s[f][2] += m1.x; s[f][3] += m1.y;
            mx0 = fmaxf(mx0, fmaxf(s[f][0], s[f][1]));
            mx1 = fmaxf(mx1, fmaxf(s[f][2], s[f][3]));
        }
        mx0 = fmaxf(mx0, __shfl_xor_sync(0xffffffffu, mx0, 1));
        mx0 = fmaxf(mx0, __shfl_xor_sync(0xffffffffu, mx0, 2));
        mx1 = fmaxf(mx1, __shfl_xor_sync(0xffffffffu, mx1, 1));
        mx1 = fmaxf(mx1, __shfl_xor_sync(0xffffffffu, mx1, 2));

        float mn0 = fmaxf(mi0, mx0), mn1 = fmaxf(mi1, mx1);
        float f0 = __expf(mi0 - mn0), f1 = __expf(mi1 - mn1);

        // P into QP (per-warp private rows)
        float rs0 = 0.0f, rs1 = 0.0f;
#pragma unroll
        for (int f = 0; f < 8; f++) {
            float p0 = __expf(s[f][0] - mn0);
            float p1 = __expf(s[f][1] - mn0);
            float p2 = __expf(s[f][2] - mn1);
            float p3 = __expf(s[f][3] - mn1);
            rs0 += p0 + p1; rs1 += p2 + p3;
            int c = f * 8 + 2 * tg;
            QP[(i0 + g) * 68 + c]         = to_tf32(p0);
            QP[(i0 + g) * 68 + c + 1]     = to_tf32(p1);
            QP[(i0 + g + 8) * 68 + c]     = to_tf32(p2);
            QP[(i0 + g + 8) * 68 + c + 1] = to_tf32(p3);
        }
        rs0 += __shfl_xor_sync(0xffffffffu, rs0, 1);
        rs0 += __shfl_xor_sync(0xffffffffu, rs0, 2);
        rs1 += __shfl_xor_sync(0xffffffffu, rs1, 1);
        rs1 += __shfl_xor_sync(0xffffffffu, rs1, 2);
        li0 = li0 * f0 + rs0; li1 = li1 * f1 + rs1;
        mi0 = mn0; mi1 = mn1;
#pragma unroll
        for (int f = 0; f < 8; f++) {
            o[f][0] *= f0; o[f][1] *= f0; o[f][2] *= f1; o[f][3] *= f1;
        }
        __syncwarp();   // P stores visible within the warp

        // O += P V   (V row-major: B(k=j, n=d) = Vb[j*72 + d])
#pragma unroll
        for (int kk = 0; kk < 8; kk++) {
            float pa[4];
            pa[0] = QP[(i0 + g) * 68 + kk * 8 + tg];
            pa[1] = QP[(i0 + g + 8) * 68 + kk * 8 + tg];
            pa[2] = QP[(i0 + g) * 68 + kk * 8 + tg + 4];
            pa[3] = QP[(i0 + g + 8) * 68 + kk * 8 + tg + 4];
#pragma unroll
            for (int f = 0; f < 8; f++) {
                float bbv[2];
                bbv[0] = Vb[(kk * 8 + tg) * 72 + f * 8 + g];
                bbv[1] = Vb[(kk * 8 + tg + 4) * 72 + f * 8 + g];
                mma8(o[f], pa, bbv);
            }
        }
        __syncwarp();   // P reads done before next iter's stores
    }

    float* yg = g_y + (size_t)(b * T_ + q0) * C_ + h * DH_;
    float inv0 = 1.0f / li0, inv1 = 1.0f / li1;
#pragma unroll
    for (int f = 0; f < 8; f++) {
        int c = f * 8 + 2 * tg;
        *(float2*)(yg + (size_t)(i0 + g) * C_ + c) =
            make_float2(to_tf32(o[f][0] * inv0), to_tf32(o[f][1] * inv0));
        *(float2*)(yg + (size_t)(i0 + g + 8) * C_ + c) =
            make_float2(to_tf32(o[f][2] * inv1), to_tf32(o[f][3] * inv1));
    }
}

// ---------------- launch ----------------
extern "C" void kernel_launch(void* const* d_in, const int* in_sizes, int n_in,
                              void* d_out, int out_size) {
    const float* x    = (const float*)d_in[0];
    // d_in[1] = context (unused by reference forward)
    const void*  mask = d_in[2];
    const float* Wq   = (const float*)d_in[3];
    const float* Wk   = (const float*)d_in[4];
    const float* Wv   = (const float*)d_in[5];
    const float* Wo   = (const float*)d_in[6];
    const float* bo   = (const float*)d_in[7];
    float* out = (float*)d_out;

    cudaFuncSetAttribute(attn_mma_kernel,
                         cudaFuncAttributeMaxDynamicSharedMemorySize,
                         ATTN_SMEM_BYTES);

    probe_mask_kernel<<<1, 256>>>((const unsigned char*)mask);
    normalize_mask_kernel<<<(B_ * T_ * T_) / 1024, 1024>>>(mask);
    round_inputs_kernel<<<(2 * M_ * C_) / 256, 256>>>(x, Wq, Wk, Wv, Wo);
    qkv_mma_kernel<<<dim3(C_ / 128, M_ / 128, 3), 256>>>();
    attn_mma_kernel<<<dim3(T_ / 64, B_ * H_), 128, ATTN_SMEM_BYTES>>>();
    proj_mma_kernel<<<dim3(C_ / 128, M_ / 128, 1), 256>>>(bo, out);
}

// round 11
// speedup vs baseline: 1.2845x; 1.2845x over previous
#include <cuda_runtime.h>
#include <math.h>
#include <stdint.h>

#define B_  4
#define T_  1024
#define C_  1024
#define H_  16
#define DH_ 64
#define M_  4096   /* B*T */

// ---------------- scratch (static __device__, no allocations) ----------------
__device__ float g_q[(size_t)M_ * C_];
__device__ float g_k[(size_t)M_ * C_];
__device__ float g_v[(size_t)M_ * C_];
__device__ float g_y[(size_t)M_ * C_];
__device__ float g_xt[(size_t)M_ * C_];          // tf32-rounded x
__device__ float g_wt[4][(size_t)C_ * C_];       // tf32-rounded Wq,Wk,Wv,Wo
__device__ float g_maskf[(size_t)B_ * T_ * T_];  // additive mask: 0 or -FLT_MAX
__device__ int g_mask_mode;   // 0 = u8 bytes, 1 = int32, 2 = float32

#define NEGF (-3.402823466e38f)

// ---------------- small helpers ----------------
__device__ __forceinline__ float to_tf32(float x) {
    uint32_t r;
    asm("cvt.rna.tf32.f32 %0, %1;" : "=r"(r) : "f"(x));
    return __uint_as_float(r);
}

__device__ __forceinline__ void mma8(float* c, const float* a, const float* b) {
    asm volatile(
        "mma.sync.aligned.m16n8k8.row.col.f32.tf32.tf32.f32 "
        "{%0,%1,%2,%3}, {%4,%5,%6,%7}, {%8,%9}, {%0,%1,%2,%3};"
        : "+f"(c[0]), "+f"(c[1]), "+f"(c[2]), "+f"(c[3])
        : "r"(__float_as_uint(a[0])), "r"(__float_as_uint(a[1])),
          "r"(__float_as_uint(a[2])), "r"(__float_as_uint(a[3])),
          "r"(__float_as_uint(b[0])), "r"(__float_as_uint(b[1])));
}

__device__ __forceinline__ void cp16(void* smem, const void* gmem) {
    uint32_t s = (uint32_t)__cvta_generic_to_shared(smem);
    asm volatile("cp.async.cg.shared.global [%0], [%1], 16;" :: "r"(s), "l"(gmem));
}
__device__ __forceinline__ void cp_commit() { asm volatile("cp.async.commit_group;"); }
template <int N>
__device__ __forceinline__ void cp_wait() { asm volatile("cp.async.wait_group %0;" :: "n"(N)); }

// ---------------- mask dtype probe + normalize ----------------
__global__ void probe_mask_kernel(const unsigned char* __restrict__ m) {
    __shared__ int s_gt1, s_nzoff;
    if (threadIdx.x == 0) { s_gt1 = 0; s_nzoff = 0; }
    __syncthreads();
    int gt1 = 0, nz = 0;
    for (int i = threadIdx.x; i < 262144; i += blockDim.x) {
        unsigned char v = m[i];
        if (v > 1) gt1 = 1;
        else if (v && (i & 3)) nz = 1;
    }
    if (gt1) atomicOr(&s_gt1, 1);
    if (nz)  atomicOr(&s_nzoff, 1);
    __syncthreads();
    if (threadIdx.x == 0)
        g_mask_mode = s_gt1 ? 2 : (s_nzoff ? 0 : 1);
}

__global__ void normalize_mask_kernel(const void* __restrict__ m) {
    int i = blockIdx.x * blockDim.x + threadIdx.x;
    int mode = g_mask_mode;
    bool keep;
    if (mode == 1)      keep = ((const int*)m)[i]   != 0;
    else if (mode == 2) keep = ((const float*)m)[i] != 0.0f;
    else                keep = ((const unsigned char*)m)[i] != 0;
    g_maskf[i] = keep ? 0.0f : NEGF;
}

// ---------------- pre-round GEMM inputs to tf32 ----------------
__global__ void round_inputs_kernel(const float* __restrict__ x,
                                    const float* __restrict__ wq,
                                    const float* __restrict__ wk,
                                    const float* __restrict__ wv,
                                    const float* __restrict__ wo) {
    int i = blockIdx.x * blockDim.x + threadIdx.x;   // 0 .. 8M-1
    if (i < M_ * C_) {
        g_xt[i] = to_tf32(x[i]);
    } else {
        int j = i - M_ * C_;
        int w = j >> 20;                  // C_*C_ = 2^20
        int r = j & (C_ * C_ - 1);
        const float* src = (w == 0) ? wq : (w == 1) ? wk : (w == 2) ? wv : wo;
        g_wt[w][r] = to_tf32(src[r]);
    }
}

// ---------------- tf32 mma NT GEMM: Out[m][n] = sum_k A[m][k]*W[n][k] ----------------
// (R6 config: fastest measured) 128x128 CTA, 128 threads, warp tile 64x64,
// k-tile 16, cp.async double buffer.
#define GS 20   /* SMEM row stride (floats): conflict-free frag loads */

__device__ __forceinline__ void gemm128(const float* __restrict__ A,
                                        const float* __restrict__ W,
                                        float* __restrict__ Out,
                                        float scale,
                                        const float* __restrict__ bias,
                                        int do_round) {
    __shared__ float As[2][128 * GS];
    __shared__ float Bs[2][128 * GS];
    const int tid  = threadIdx.x;
    const int warp = tid >> 5, lane = tid & 31;
    const int g = lane >> 2, tg = lane & 3;
    const int wm = warp >> 1, wn = warp & 1;
    const int m0 = blockIdx.y * 128, n0 = blockIdx.x * 128;

    float acc[4][8][4];
#pragma unroll
    for (int mf = 0; mf < 4; mf++)
#pragma unroll
        for (int nf = 0; nf < 8; nf++)
#pragma unroll
            for (int q = 0; q < 4; q++) acc[mf][nf][q] = 0.0f;

#pragma unroll
    for (int i = 0; i < 4; i++) {       // prologue: tile 0 (128 rows x 16 floats)
        int chunk = i * 128 + tid, row = chunk >> 2, c4 = (chunk & 3) * 4;
        cp16(&As[0][row * GS + c4], A + (size_t)(m0 + row) * C_ + c4);
        cp16(&Bs[0][row * GS + c4], W + (size_t)(n0 + row) * C_ + c4);
    }
    cp_commit();

    for (int kt = 0; kt < 64; kt++) {
        int buf = kt & 1;
        if (kt < 63) {
#pragma unroll
            for (int i = 0; i < 4; i++) {
                int chunk = i * 128 + tid, row = chunk >> 2, c4 = (chunk & 3) * 4;
                cp16(&As[buf ^ 1][row * GS + c4],
                     A + (size_t)(m0 + row) * C_ + (kt + 1) * 16 + c4);
                cp16(&Bs[buf ^ 1][row * GS + c4],
                     W + (size_t)(n0 + row) * C_ + (kt + 1) * 16 + c4);
            }
            cp_commit();
            cp_wait<1>();
        } else {
            cp_wait<0>();
        }
        __syncthreads();
        const float* as = As[buf];
        const float* bs = Bs[buf];
#pragma unroll
        for (int ks = 0; ks < 2; ks++) {
            const int k0 = ks * 8;
            float a[4][4], b[8][2];
#pragma unroll
            for (int mf = 0; mf < 4; mf++) {
                int r = wm * 64 + mf * 16 + g;
                a[mf][0] = as[r * GS + k0 + tg];
                a[mf][1] = as[(r + 8) * GS + k0 + tg];
                a[mf][2] = as[r * GS + k0 + tg + 4];
                a[mf][3] = as[(r + 8) * GS + k0 + tg + 4];
            }
#pragma unroll
            for (int nf = 0; nf < 8; nf++) {
                int c = wn * 64 + nf * 8 + g;
                b[nf][0] = bs[c * GS + k0 + tg];
                b[nf][1] = bs[c * GS + k0 + tg + 4];
            }
#pragma unroll
            for (int mf = 0; mf < 4; mf++)
#pragma unroll
                for (int nf = 0; nf < 8; nf++)
                    mma8(acc[mf][nf], a[mf], b[nf]);
        }
        __syncthreads();
    }

#pragma unroll
    for (int mf = 0; mf < 4; mf++) {
        int r0 = m0 + wm * 64 + mf * 16 + g;
#pragma unroll
        for (int nf = 0; nf < 8; nf++) {
            int c = n0 + wn * 64 + nf * 8 + 2 * tg;
            float v0 = acc[mf][nf][0] * scale, v1 = acc[mf][nf][1] * scale;
            float v2 = acc[mf][nf][2] * scale, v3 = acc[mf][nf][3] * scale;
            if (bias) { v0 += bias[c]; v1 += bias[c + 1]; v2 += bias[c]; v3 += bias[c + 1]; }
            if (do_round) { v0 = to_tf32(v0); v1 = to_tf32(v1); v2 = to_tf32(v2); v3 = to_tf32(v3); }
            *(float2*)(Out + (size_t)r0 * C_ + c)       = make_float2(v0, v1);
            *(float2*)(Out + (size_t)(r0 + 8) * C_ + c) = make_float2(v2, v3);
        }
    }
}

__global__ __launch_bounds__(128) void qkv_mma_kernel() {
    if (blockIdx.z == 0)      gemm128(g_xt, g_wt[0], g_q, 0.125f, nullptr, 1);
    else if (blockIdx.z == 1) gemm128(g_xt, g_wt[1], g_k, 1.0f,  nullptr, 1);
    else                      gemm128(g_xt, g_wt[2], g_v, 1.0f,  nullptr, 1);
}

__global__ __launch_bounds__(128) void proj_mma_kernel(const float* __restrict__ bo,
                                                       float* __restrict__ out) {
    gemm128(g_y, g_wt[3], out, 1.0f, bo, 0);
}

// ---------------- tf32 mma flash attention ----------------
// grid (T/128, B*H), 256 threads (8 warps). Warp w owns q rows [16w,16w+16).
// 128-row Q tile: each 64-row K/V tile is reused by 2x the mma work vs 64-row Q.
// Q staged into QP then register fragments; QP rows then hold P (warp-private).
// K stride 68, V row-major stride 72 -> all fragment LDS conflict-free.
// Single-buffer K/V, 2 syncthreads per iteration. SMEM 69KB -> 2 CTAs/SM.
#define QP_OFF 0               /* 128*68 floats */
#define K_OFF  8704
#define V_OFF  13056           /* K_OFF + 64*68 */
#define ATTN_SMEM_BYTES ((13056 + 64 * 72) * 4)   /* 70656 */

__global__ __launch_bounds__(256, 2) void attn_mma_kernel() {
    extern __shared__ float sm[];
    float* QP = sm + QP_OFF;
    float* Kb = sm + K_OFF;
    float* Vb = sm + V_OFF;
    const int tid  = threadIdx.x;
    const int warp = tid >> 5, lane = tid & 31;
    const int g = lane >> 2, tg = lane & 3;
    const int i0 = warp * 16;
    const int bh = blockIdx.y, b = bh >> 4, h = bh & 15;
    const int q0 = blockIdx.x * 128;

    const float* qg = g_q + (size_t)(b * T_ + q0) * C_ + h * DH_;
    const float* kg = g_k + (size_t)(b * T_) * C_ + h * DH_;
    const float* vg = g_v + (size_t)(b * T_) * C_ + h * DH_;
    const float* mrow0f = g_maskf + (size_t)(b * T_ + q0 + i0 + g) * T_;
    const float* mrow1f = mrow0f + (size_t)8 * T_;

    // stage Q tile (128 rows x 64 floats = 2048 float4 chunks)
#pragma unroll
    for (int i = 0; i < 8; i++) {
        int chunk = i * 256 + tid, row = chunk >> 4, c4 = (chunk & 15) * 4;
        float4 v = *(const float4*)(qg + (size_t)row * C_ + c4);
        *(float4*)&QP[row * 68 + c4] = v;
    }
    __syncthreads();

    float qa[8][4];
#pragma unroll
    for (int kk = 0; kk < 8; kk++) {
        qa[kk][0] = QP[(i0 + g) * 68 + kk * 8 + tg];
        qa[kk][1] = QP[(i0 + g + 8) * 68 + kk * 8 + tg];
        qa[kk][2] = QP[(i0 + g) * 68 + kk * 8 + tg + 4];
        qa[kk][3] = QP[(i0 + g + 8) * 68 + kk * 8 + tg + 4];
    }

    float o[8][4];
#pragma unroll
    for (int f = 0; f < 8; f++)
#pragma unroll
        for (int q = 0; q < 4; q++) o[f][q] = 0.0f;
    float mi0 = NEGF, mi1 = NEGF, li0 = 0.0f, li1 = 0.0f;

    for (int it = 0; it < 16; it++) {
        __syncthreads();   // prior iter's K/V consumers done (Q staging on it=0)
        // load K/V tile (64 rows x 64 floats = 1024 chunks / 256 thr)
        const float* kn = kg + (size_t)it * 64 * C_;
        const float* vn = vg + (size_t)it * 64 * C_;
#pragma unroll
        for (int i = 0; i < 4; i++) {
            int chunk = i * 256 + tid, row = chunk >> 4, c4 = (chunk & 15) * 4;
            float4 kv = *(const float4*)(kn + (size_t)row * C_ + c4);
            *(float4*)&Kb[row * 68 + c4] = kv;
            float4 vv = *(const float4*)(vn + (size_t)row * C_ + c4);
            *(float4*)&Vb[row * 72 + c4] = vv;
        }
        __syncthreads();

        // S = Q K^T (16x64 per warp)
        float s[8][4];
#pragma unroll
        for (int f = 0; f < 8; f++)
#pragma unroll
            for (int q = 0; q < 4; q++) s[f][q] = 0.0f;
#pragma unroll
        for (int kk = 0; kk < 8; kk++) {
#pragma unroll
            for (int f = 0; f < 8; f++) {
                float bbk[2];
                bbk[0] = Kb[(f * 8 + g) * 68 + kk * 8 + tg];
                bbk[1] = Kb[(f * 8 + g) * 68 + kk * 8 + tg + 4];
                mma8(s[f], qa[kk], bbk);
            }
        }

        // additive mask + row max
        const int jt = it * 64;
        float mx0 = NEGF, mx1 = NEGF;
#pragma unroll
        for (int f = 0; f < 8; f++) {
            int c = jt + f * 8 + 2 * tg;
            float2 m0 = *(const float2*)(mrow0f + c);
            float2 m1 = *(const float2*)(mrow1f + c);
            s[f][0] += m0.x; s[f][1] += m0.y;
            s[f][2] += m1.x; s[f][3] += m1.y;
            mx0 = fmaxf(mx0, fmaxf(s[f][0], s[f][1]));
            mx1 = fmaxf(mx1, fmaxf(s[f][2], s[f][3]));
        }
        mx0 = fmaxf(mx0, __shfl_xor_sync(0xffffffffu, mx0, 1));
        mx0 = fmaxf(mx0, __shfl_xor_sync(0xffffffffu, mx0, 2));
        mx1 = fmaxf(mx1, __shfl_xor_sync(0xffffffffu, mx1, 1));
        mx1 = fmaxf(mx1, __shfl_xor_sync(0xffffffffu, mx1, 2));

        float mn0 = fmaxf(mi0, mx0), mn1 = fmaxf(mi1, mx1);
        float f0 = __expf(mi0 - mn0), f1 = __expf(mi1 - mn1);

        // P into QP (warp-private rows; Q already in registers)
        float rs0 = 0.0f, rs1 = 0.0f;
#pragma unroll
        for (int f = 0; f < 8; f++) {
            float p0 = __expf(s[f][0] - mn0);
            float p1 = __expf(s[f][1] - mn0);
            float p2 = __expf(s[f][2] - mn1);
            float p3 = __expf(s[f][3] - mn1);
            rs0 += p0 + p1; rs1 += p2 + p3;
            int c = f * 8 + 2 * tg;
            QP[(i0 + g) * 68 + c]         = to_tf32(p0);
            QP[(i0 + g) * 68 + c + 1]     = to_tf32(p1);
            QP[(i0 + g + 8) * 68 + c]     = to_tf32(p2);
            QP[(i0 + g + 8) * 68 + c + 1] = to_tf32(p3);
        }
        rs0 += __shfl_xor_sync(0xffffffffu, rs0, 1);
        rs0 += __shfl_xor_sync(0xffffffffu, rs0, 2);
        rs1 += __shfl_xor_sync(0xffffffffu, rs1, 1);
        rs1 += __shfl_xor_sync(0xffffffffu, rs1, 2);
        li0 = li0 * f0 + rs0; li1 = li1 * f1 + rs1;
        mi0 = mn0; mi1 = mn1;
#pragma unroll
        for (int f = 0; f < 8; f++) {
            o[f][0] *= f0; o[f][1] *= f0; o[f][2] *= f1; o[f][3] *= f1;
        }
        __syncwarp();   // P stores visible within the warp

        // O += P V   (V row-major: B(k=j, n=d) = Vb[j*72 + d])
#pragma unroll
        for (int kk = 0; kk < 8; kk++) {
            float pa[4];
            pa[0] = QP[(i0 + g) * 68 + kk * 8 + tg];
            pa[1] = QP[(i0 + g + 8) * 68 + kk * 8 + tg];
            pa[2] = QP[(i0 + g) * 68 + kk * 8 + tg + 4];
            pa[3] = QP[(i0 + g + 8) * 68 + kk * 8 + tg + 4];
#pragma unroll
            for (int f = 0; f < 8; f++) {
                float bbv[2];
                bbv[0] = Vb[(kk * 8 + tg) * 72 + f * 8 + g];
                bbv[1] = Vb[(kk * 8 + tg + 4) * 72 + f * 8 + g];
                mma8(o[f], pa, bbv);
            }
        }
    }

    float* yg = g_y + (size_t)(b * T_ + q0) * C_ + h * DH_;
    float inv0 = 1.0f / li0, inv1 = 1.0f / li1;
#pragma unroll
    for (int f = 0; f < 8; f++) {
        int c = f * 8 + 2 * tg;
        *(float2*)(yg + (size_t)(i0 + g) * C_ + c) =
            make_float2(to_tf32(o[f][0] * inv0), to_tf32(o[f][1] * inv0));
        *(float2*)(yg + (size_t)(i0 + g + 8) * C_ + c) =
            make_float2(to_tf32(o[f][2] * inv1), to_tf32(o[f][3] * inv1));
    }
}

// ---------------- launch ----------------
extern "C" void kernel_launch(void* const* d_in, const int* in_sizes, int n_in,
                              void* d_out, int out_size) {
    const float* x    = (const float*)d_in[0];
    // d_in[1] = context (unused by reference forward)
    const void*  mask = d_in[2];
    const float* Wq   = (const float*)d_in[3];
    const float* Wk   = (const float*)d_in[4];
    const float* Wv   = (const float*)d_in[5];
    const float* Wo   = (const float*)d_in[6];
    const float* bo   = (const float*)d_in[7];
    float* out = (float*)d_out;

    cudaFuncSetAttribute(attn_mma_kernel,
                         cudaFuncAttributeMaxDynamicSharedMemorySize,
                         ATTN_SMEM_BYTES);

    probe_mask_kernel<<<1, 256>>>((const unsigned char*)mask);
    normalize_mask_kernel<<<(B_ * T_ * T_) / 1024, 1024>>>(mask);
    round_inputs_kernel<<<(2 * M_ * C_) / 256, 256>>>(x, Wq, Wk, Wv, Wo);
    qkv_mma_kernel<<<dim3(C_ / 128, M_ / 128, 3), 128>>>();
    attn_mma_kernel<<<dim3(T_ / 128, B_ * H_), 256, ATTN_SMEM_BYTES>>>();
    proj_mma_kernel<<<dim3(C_ / 128, M_ / 128, 1), 128>>>(bo, out);
}

// round 13
// speedup vs baseline: 1.3541x; 1.0542x over previous
#include <cuda_runtime.h>
#include <math.h>
#include <stdint.h>

#define B_  4
#define T_  1024
#define C_  1024
#define H_  16
#define DH_ 64
#define M_  4096   /* B*T */

// ---------------- scratch (static __device__, no allocations) ----------------
__device__ float g_q[(size_t)M_ * C_];
__device__ float g_k[(size_t)M_ * C_];
__device__ float g_v[(size_t)M_ * C_];
__device__ float g_y[(size_t)M_ * C_];
__device__ float g_xt[(size_t)M_ * C_];          // tf32-rounded x
__device__ float g_wt[4][(size_t)C_ * C_];       // tf32-rounded Wq,Wk,Wv,Wo
__device__ float g_maskf[(size_t)B_ * T_ * T_];  // additive mask: 0 or -FLT_MAX
__device__ int g_mask_mode;   // 0 = u8 bytes, 1 = int32, 2 = float32

#define NEGF (-3.402823466e38f)

// ---------------- small helpers ----------------
__device__ __forceinline__ float to_tf32(float x) {
    uint32_t r;
    asm("cvt.rna.tf32.f32 %0, %1;" : "=r"(r) : "f"(x));
    return __uint_as_float(r);
}

__device__ __forceinline__ void mma8(float* c, const float* a, const float* b) {
    asm volatile(
        "mma.sync.aligned.m16n8k8.row.col.f32.tf32.tf32.f32 "
        "{%0,%1,%2,%3}, {%4,%5,%6,%7}, {%8,%9}, {%0,%1,%2,%3};"
        : "+f"(c[0]), "+f"(c[1]), "+f"(c[2]), "+f"(c[3])
        : "r"(__float_as_uint(a[0])), "r"(__float_as_uint(a[1])),
          "r"(__float_as_uint(a[2])), "r"(__float_as_uint(a[3])),
          "r"(__float_as_uint(b[0])), "r"(__float_as_uint(b[1])));
}

__device__ __forceinline__ void cp16(void* smem, const void* gmem) {
    uint32_t s = (uint32_t)__cvta_generic_to_shared(smem);
    asm volatile("cp.async.cg.shared.global [%0], [%1], 16;" :: "r"(s), "l"(gmem));
}
__device__ __forceinline__ void cp_commit() { asm volatile("cp.async.commit_group;"); }
template <int N>
__device__ __forceinline__ void cp_wait() { asm volatile("cp.async.wait_group %0;" :: "n"(N)); }

// ---------------- mask dtype probe + normalize ----------------
__global__ void probe_mask_kernel(const unsigned char* __restrict__ m) {
    __shared__ int s_gt1, s_nzoff;
    if (threadIdx.x == 0) { s_gt1 = 0; s_nzoff = 0; }
    __syncthreads();
    int gt1 = 0, nz = 0;
    for (int i = threadIdx.x; i < 262144; i += blockDim.x) {
        unsigned char v = m[i];
        if (v > 1) gt1 = 1;
        else if (v && (i & 3)) nz = 1;
    }
    if (gt1) atomicOr(&s_gt1, 1);
    if (nz)  atomicOr(&s_nzoff, 1);
    __syncthreads();
    if (threadIdx.x == 0)
        g_mask_mode = s_gt1 ? 2 : (s_nzoff ? 0 : 1);
}

__global__ void normalize_mask_kernel(const void* __restrict__ m) {
    int i = blockIdx.x * blockDim.x + threadIdx.x;
    int mode = g_mask_mode;
    bool keep;
    if (mode == 1)      keep = ((const int*)m)[i]   != 0;
    else if (mode == 2) keep = ((const float*)m)[i] != 0.0f;
    else                keep = ((const unsigned char*)m)[i] != 0;
    g_maskf[i] = keep ? 0.0f : NEGF;
}

// ---------------- pre-round GEMM inputs to tf32 (float4 vectorized) ----------------
__global__ void round_inputs_kernel(const float* __restrict__ x,
                                    const float* __restrict__ wq,
                                    const float* __restrict__ wk,
                                    const float* __restrict__ wv,
                                    const float* __restrict__ wo) {
    int idx = blockIdx.x * blockDim.x + threadIdx.x;   // 0 .. 2M-1 (float4 units)
    int i4 = idx * 4;
    if (i4 < M_ * C_) {
        float4 v = *(const float4*)(x + i4);
        v.x = to_tf32(v.x); v.y = to_tf32(v.y);
        v.z = to_tf32(v.z); v.w = to_tf32(v.w);
        *(float4*)(g_xt + i4) = v;
    } else {
        int j = i4 - M_ * C_;
        int w = j >> 20;                  // C_*C_ = 2^20
        int r = j & (C_ * C_ - 1);
        const float* src = (w == 0) ? wq : (w == 1) ? wk : (w == 2) ? wv : wo;
        float4 v = *(const float4*)(src + r);
        v.x = to_tf32(v.x); v.y = to_tf32(v.y);
        v.z = to_tf32(v.z); v.w = to_tf32(v.w);
        *(float4*)(&g_wt[w][r]) = v;
    }
}

// ---------------- tf32 mma NT GEMM: Out[m][n] = sum_k A[m][k]*W[n][k] ----------------
// (R6 config: fastest measured) 128x128 CTA, 128 threads, warp tile 64x64,
// k-tile 16, cp.async double buffer.
#define GS 20   /* SMEM row stride (floats): conflict-free frag loads */

__device__ __forceinline__ void gemm128(const float* __restrict__ A,
                                        const float* __restrict__ W,
                                        float* __restrict__ Out,
                                        float scale,
                                        const float* __restrict__ bias,
                                        int do_round) {
    __shared__ float As[2][128 * GS];
    __shared__ float Bs[2][128 * GS];
    const int tid  = threadIdx.x;
    const int warp = tid >> 5, lane = tid & 31;
    const int g = lane >> 2, tg = lane & 3;
    const int wm = warp >> 1, wn = warp & 1;
    const int m0 = blockIdx.y * 128, n0 = blockIdx.x * 128;

    float acc[4][8][4];
#pragma unroll
    for (int mf = 0; mf < 4; mf++)
#pragma unroll
        for (int nf = 0; nf < 8; nf++)
#pragma unroll
            for (int q = 0; q < 4; q++) acc[mf][nf][q] = 0.0f;

#pragma unroll
    for (int i = 0; i < 4; i++) {       // prologue: tile 0 (128 rows x 16 floats)
        int chunk = i * 128 + tid, row = chunk >> 2, c4 = (chunk & 3) * 4;
        cp16(&As[0][row * GS + c4], A + (size_t)(m0 + row) * C_ + c4);
        cp16(&Bs[0][row * GS + c4], W + (size_t)(n0 + row) * C_ + c4);
    }
    cp_commit();

    for (int kt = 0; kt < 64; kt++) {
        int buf = kt & 1;
        if (kt < 63) {
#pragma unroll
            for (int i = 0; i < 4; i++) {
                int chunk = i * 128 + tid, row = chunk >> 2, c4 = (chunk & 3) * 4;
                cp16(&As[buf ^ 1][row * GS + c4],
                     A + (size_t)(m0 + row) * C_ + (kt + 1) * 16 + c4);
                cp16(&Bs[buf ^ 1][row * GS + c4],
                     W + (size_t)(n0 + row) * C_ + (kt + 1) * 16 + c4);
            }
            cp_commit();
            cp_wait<1>();
        } else {
            cp_wait<0>();
        }
        __syncthreads();
        const float* as = As[buf];
        const float* bs = Bs[buf];
#pragma unroll
        for (int ks = 0; ks < 2; ks++) {
            const int k0 = ks * 8;
            float a[4][4], b[8][2];
#pragma unroll
            for (int mf = 0; mf < 4; mf++) {
                int r = wm * 64 + mf * 16 + g;
                a[mf][0] = as[r * GS + k0 + tg];
                a[mf][1] = as[(r + 8) * GS + k0 + tg];
                a[mf][2] = as[r * GS + k0 + tg + 4];
                a[mf][3] = as[(r + 8) * GS + k0 + tg + 4];
            }
#pragma unroll
            for (int nf = 0; nf < 8; nf++) {
                int c = wn * 64 + nf * 8 + g;
                b[nf][0] = bs[c * GS + k0 + tg];
                b[nf][1] = bs[c * GS + k0 + tg + 4];
            }
#pragma unroll
            for (int mf = 0; mf < 4; mf++)
#pragma unroll
                for (int nf = 0; nf < 8; nf++)
                    mma8(acc[mf][nf], a[mf], b[nf]);
        }
        __syncthreads();
    }

#pragma unroll
    for (int mf = 0; mf < 4; mf++) {
        int r0 = m0 + wm * 64 + mf * 16 + g;
#pragma unroll
        for (int nf = 0; nf < 8; nf++) {
            int c = n0 + wn * 64 + nf * 8 + 2 * tg;
            float v0 = acc[mf][nf][0] * scale, v1 = acc[mf][nf][1] * scale;
            float v2 = acc[mf][nf][2] * scale, v3 = acc[mf][nf][3] * scale;
            if (bias) { v0 += bias[c]; v1 += bias[c + 1]; v2 += bias[c]; v3 += bias[c + 1]; }
            if (do_round) { v0 = to_tf32(v0); v1 = to_tf32(v1); v2 = to_tf32(v2); v3 = to_tf32(v3); }
            *(float2*)(Out + (size_t)r0 * C_ + c)       = make_float2(v0, v1);
            *(float2*)(Out + (size_t)(r0 + 8) * C_ + c) = make_float2(v2, v3);
        }
    }
}

__global__ __launch_bounds__(128) void qkv_mma_kernel() {
    if (blockIdx.z == 0)      gemm128(g_xt, g_wt[0], g_q, 0.125f, nullptr, 1);
    else if (blockIdx.z == 1) gemm128(g_xt, g_wt[1], g_k, 1.0f,  nullptr, 1);
    else                      gemm128(g_xt, g_wt[2], g_v, 1.0f,  nullptr, 1);
}

__global__ __launch_bounds__(128) void proj_mma_kernel(const float* __restrict__ bo,
                                                       float* __restrict__ out) {
    gemm128(g_y, g_wt[3], out, 1.0f, bo, 0);
}

// ---------------- tf32 mma flash attention ----------------
// grid (T/128, B*H), 256 threads (8 warps). Warp w owns q rows [16w,16w+16).
// 128-row Q tile + cp.async DOUBLE-buffered 64-row K/V tiles.
// SMEM 106.5KB -> 2 CTAs/SM (16 warps) AND gmem latency hidden.
// Q staged then held in registers; QP rows then hold P (warp-private).
// K stride 68, V row-major stride 72 -> all fragment LDS conflict-free.
#define QP_OFF 0               /* 128*68 floats */
#define K_OFF  8704
#define K_SZ   4352            /* 64*68 */
#define V_OFF  17408           /* K_OFF + 2*K_SZ */
#define V_SZ   4608            /* 64*72 */
#define ATTN_SMEM_BYTES ((17408 + 2 * 4608) * 4)   /* 106496 */

__global__ __launch_bounds__(256, 2) void attn_mma_kernel() {
    extern __shared__ float sm[];
    float* QP = sm + QP_OFF;
    const int tid  = threadIdx.x;
    const int warp = tid >> 5, lane = tid & 31;
    const int g = lane >> 2, tg = lane & 3;
    const int i0 = warp * 16;
    const int bh = blockIdx.y, b = bh >> 4, h = bh & 15;
    const int q0 = blockIdx.x * 128;

    const float* qg = g_q + (size_t)(b * T_ + q0) * C_ + h * DH_;
    const float* kg = g_k + (size_t)(b * T_) * C_ + h * DH_;
    const float* vg = g_v + (size_t)(b * T_) * C_ + h * DH_;
    const float* mrow0f = g_maskf + (size_t)(b * T_ + q0 + i0 + g) * T_;
    const float* mrow1f = mrow0f + (size_t)8 * T_;

    // stage Q tile (128 rows x 64 floats = 2048 float4 chunks)
#pragma unroll
    for (int i = 0; i < 8; i++) {
        int chunk = i * 256 + tid, row = chunk >> 4, c4 = (chunk & 15) * 4;
        float4 v = *(const float4*)(qg + (size_t)row * C_ + c4);
        *(float4*)&QP[row * 68 + c4] = v;
    }
    // prefetch K/V tile 0 into buffer 0 (64 rows x 16 float4 = 1024 chunks)
#pragma unroll
    for (int i = 0; i < 4; i++) {
        int chunk = i * 256 + tid, row = chunk >> 4, c4 = (chunk & 15) * 4;
        cp16(&sm[K_OFF + row * 68 + c4], kg + (size_t)row * C_ + c4);
        cp16(&sm[V_OFF + row * 72 + c4], vg + (size_t)row * C_ + c4);
    }
    cp_commit();
    __syncthreads();   // Q staging visible

    float qa[8][4];
#pragma unroll
    for (int kk = 0; kk < 8; kk++) {
        qa[kk][0] = QP[(i0 + g) * 68 + kk * 8 + tg];
        qa[kk][1] = QP[(i0 + g + 8) * 68 + kk * 8 + tg];
        qa[kk][2] = QP[(i0 + g) * 68 + kk * 8 + tg + 4];
        qa[kk][3] = QP[(i0 + g + 8) * 68 + kk * 8 + tg + 4];
    }

    float o[8][4];
#pragma unroll
    for (int f = 0; f < 8; f++)
#pragma unroll
        for (int q = 0; q < 4; q++) o[f][q] = 0.0f;
    float mi0 = NEGF, mi1 = NEGF, li0 = 0.0f, li1 = 0.0f;

    for (int it = 0; it < 16; it++) {
        const int bb = it & 1;
        const float* Kb = sm + K_OFF + bb * K_SZ;
        const float* Vb = sm + V_OFF + bb * V_SZ;
        cp_wait<0>();
        __syncthreads();   // tile it ready; all warps done with buffer bb^1
        if (it < 15) {     // prefetch next tile into other buffer
            const float* kn = kg + (size_t)(it + 1) * 64 * C_;
            const float* vn = vg + (size_t)(it + 1) * 64 * C_;
            float* Kn = sm + K_OFF + (bb ^ 1) * K_SZ;
            float* Vn = sm + V_OFF + (bb ^ 1) * V_SZ;
#pragma unroll
            for (int i = 0; i < 4; i++) {
                int chunk = i * 256 + tid, row = chunk >> 4, c4 = (chunk & 15) * 4;
                cp16(&Kn[row * 68 + c4], kn + (size_t)row * C_ + c4);
                cp16(&Vn[row * 72 + c4], vn + (size_t)row * C_ + c4);
            }
            cp_commit();
        }

        // S = Q K^T (16x64 per warp)
        float s[8][4];
#pragma unroll
        for (int f = 0; f < 8; f++)
#pragma unroll
            for (int q = 0; q < 4; q++) s[f][q] = 0.0f;
#pragma unroll
        for (int kk = 0; kk < 8; kk++) {
#pragma unroll
            for (int f = 0; f < 8; f++) {
                float bbk[2];
                bbk[0] = Kb[(f * 8 + g) * 68 + kk * 8 + tg];
                bbk[1] = Kb[(f * 8 + g) * 68 + kk * 8 + tg + 4];
                mma8(s[f], qa[kk], bbk);
            }
        }

        // additive mask + row max
        const int jt = it * 64;
        float mx0 = NEGF, mx1 = NEGF;
#pragma unroll
        for (int f = 0; f < 8; f++) {
            int c = jt + f * 8 + 2 * tg;
            float2 m0 = *(const float2*)(mrow0f + c);
            float2 m1 = *(const float2*)(mrow1f + c);
            s[f][0] += m0.x; s[f][1] += m0.y;
            s[f][2] += m1.x; s[f][3] += m1.y;
            mx0 = fmaxf(mx0, fmaxf(s[f][0], s[f][1]));
            mx1 = fmaxf(mx1, fmaxf(s[f][2], s[f][3]));
        }
        mx0 = fmaxf(mx0, __shfl_xor_sync(0xffffffffu, mx0, 1));
        mx0 = fmaxf(mx0, __shfl_xor_sync(0xffffffffu, mx0, 2));
        mx1 = fmaxf(mx1, __shfl_xor_sync(0xffffffffu, mx1, 1));
        mx1 = fmaxf(mx1, __shfl_xor_sync(0xffffffffu, mx1, 2));

        float mn0 = fmaxf(mi0, mx0), mn1 = fmaxf(mi1, mx1);
        float f0 = __expf(mi0 - mn0), f1 = __expf(mi1 - mn1);

        // P into QP (warp-private rows; Q already in registers)
        float rs0 = 0.0f, rs1 = 0.0f;
#pragma unroll
        for (int f = 0; f < 8; f++) {
            float p0 = __expf(s[f][0] - mn0);
            float p1 = __expf(s[f][1] - mn0);
            float p2 = __expf(s[f][2] - mn1);
            float p3 = __expf(s[f][3] - mn1);
            rs0 += p0 + p1; rs1 += p2 + p3;
            int c = f * 8 + 2 * tg;
            QP[(i0 + g) * 68 + c]         = to_tf32(p0);
            QP[(i0 + g) * 68 + c + 1]     = to_tf32(p1);
            QP[(i0 + g + 8) * 68 + c]     = to_tf32(p2);
            QP[(i0 + g + 8) * 68 + c + 1] = to_tf32(p3);
        }
        rs0 += __shfl_xor_sync(0xffffffffu, rs0, 1);
        rs0 += __shfl_xor_sync(0xffffffffu, rs0, 2);
        rs1 += __shfl_xor_sync(0xffffffffu, rs1, 1);
        rs1 += __shfl_xor_sync(0xffffffffu, rs1, 2);
        li0 = li0 * f0 + rs0; li1 = li1 * f1 + rs1;
        mi0 = mn0; mi1 = mn1;
#pragma unroll
        for (int f = 0; f < 8; f++) {
            o[f][0] *= f0; o[f][1] *= f0; o[f][2] *= f1; o[f][3] *= f1;
        }
        __syncwarp();   // P stores visible within the warp

        // O += P V   (V row-major: B(k=j, n=d) = Vb[j*72 + d])
#pragma unroll
        for (int kk = 0; kk < 8; kk++) {
            float pa[4];
            pa[0] = QP[(i0 + g) * 68 + kk * 8 + tg];
            pa[1] = QP[(i0 + g + 8) * 68 + kk * 8 + tg];
            pa[2] = QP[(i0 + g) * 68 + kk * 8 + tg + 4];
            pa[3] = QP[(i0 + g + 8) * 68 + kk * 8 + tg + 4];
#pragma unroll
            for (int f = 0; f < 8; f++) {
                float bbv[2];
                bbv[0] = Vb[(kk * 8 + tg) * 72 + f * 8 + g];
                bbv[1] = Vb[(kk * 8 + tg + 4) * 72 + f * 8 + g];
                mma8(o[f], pa, bbv);
            }
        }
        __syncwarp();   // P reads done before next iter's stores
    }

    float* yg = g_y + (size_t)(b * T_ + q0) * C_ + h * DH_;
    float inv0 = 1.0f / li0, inv1 = 1.0f / li1;
#pragma unroll
    for (int f = 0; f < 8; f++) {
        int c = f * 8 + 2 * tg;
        *(float2*)(yg + (size_t)(i0 + g) * C_ + c) =
            make_float2(to_tf32(o[f][0] * inv0), to_tf32(o[f][1] * inv0));
        *(float2*)(yg + (size_t)(i0 + g + 8) * C_ + c) =
            make_float2(to_tf32(o[f][2] * inv1), to_tf32(o[f][3] * inv1));
    }
}

// ---------------- launch ----------------
extern "C" void kernel_launch(void* const* d_in, const int* in_sizes, int n_in,
                              void* d_out, int out_size) {
    const float* x    = (const float*)d_in[0];
    // d_in[1] = context (unused by reference forward)
    const void*  mask = d_in[2];
    const float* Wq   = (const float*)d_in[3];
    const float* Wk   = (const float*)d_in[4];
    const float* Wv   = (const float*)d_in[5];
    const float* Wo   = (const float*)d_in[6];
    const float* bo   = (const float*)d_in[7];
    float* out = (float*)d_out;

    cudaFuncSetAttribute(attn_mma_kernel,
                         cudaFuncAttributeMaxDynamicSharedMemorySize,
                         ATTN_SMEM_BYTES);

    probe_mask_kernel<<<1, 256>>>((const unsigned char*)mask);
    normalize_mask_kernel<<<(B_ * T_ * T_) / 1024, 1024>>>(mask);
    round_inputs_kernel<<<(2 * M_ * C_) / 1024, 256>>>(x, Wq, Wk, Wv, Wo);
    qkv_mma_kernel<<<dim3(C_ / 128, M_ / 128, 3), 128>>>();
    attn_mma_kernel<<<dim3(T_ / 128, B_ * H_), 256, ATTN_SMEM_BYTES>>>();
    proj_mma_kernel<<<dim3(C_ / 128, M_ / 128, 1), 128>>>(bo, out);
}